// round 3
// baseline (speedup 1.0000x reference)
#include <cuda_runtime.h>
#include <math.h>

#define BB 128
#define TT 512
#define DD 100
#define HH 100
#define G4 400
#define LL 25
#define EMS 26   // padded emission stride (aligned float2 pairs)

typedef unsigned long long ull;

// ---------------- device scratch (static; no runtime allocation) ----------------
__device__ float g_gin[2][TT][BB][G4];          // input projection + biases
__device__ float g_h[2][TT][BB][HH];            // hidden states, both dirs
__device__ float g_em[(size_t)BB * TT * EMS];   // emissions [b][t][l], stride 26
__device__ float g_res[BB];                     // per-batch logZ - gold

// ---------------- helpers ----------------
__device__ __forceinline__ float sigf(float x) {
    return __fdividef(1.f, 1.f + __expf(-x));
}
__device__ __forceinline__ float tanh_fast(float x) {
    return __fdividef(2.f, 1.f + __expf(-2.f * x)) - 1.f;
}
__device__ __forceinline__ ull ffma2(ull a, ull b, ull c) {
    ull d;
    asm("fma.rn.f32x2 %0, %1, %2, %3;" : "=l"(d) : "l"(a), "l"(b), "l"(c));
    return d;
}
__device__ __forceinline__ ull fadd2(ull a, ull b) {
    ull d;
    asm("add.rn.f32x2 %0, %1, %2;" : "=l"(d) : "l"(a), "l"(b));
    return d;
}
__device__ __forceinline__ ull fmul2(ull a, ull b) {
    ull d;
    asm("mul.rn.f32x2 %0, %1, %2;" : "=l"(d) : "l"(a), "l"(b));
    return d;
}
__device__ __forceinline__ float2 u2f(ull u) {
    float2 f;
    asm("mov.b64 {%0, %1}, %2;" : "=f"(f.x), "=f"(f.y) : "l"(u));
    return f;
}
__device__ __forceinline__ ull f2u(float x, float y) {
    ull u;
    asm("mov.b64 %0, {%1, %2};" : "=l"(u) : "f"(x), "f"(y));
    return u;
}

// ================= Kernel 1: embedding lookup + input projection GEMM =================
// gin[dir][t][b][col] = sum_d emb[tok[b][t]][d]*W[col][d] + bias
// block: rows = batch b (128), t = blockIdx.x; 64 cols (blockIdx.y); 256 threads,
// thread tile 4 rows x 8 cols, f32x2 k-pair packing.
#define XS_STRIDE 102
#define PROJ_SMEM ((128 * XS_STRIDE + 64 * XS_STRIDE) * 4)

__global__ void __launch_bounds__(256) k_input_proj(
    const int* __restrict__ tok, const float* __restrict__ emb,
    const float* __restrict__ wih_f, const float* __restrict__ wih_b,
    const float* __restrict__ bih_f, const float* __restrict__ bhh_f,
    const float* __restrict__ bih_b, const float* __restrict__ bhh_b)
{
    extern __shared__ float psm[];
    float* xs = psm;                    // [128][102]
    float* wc = psm + 128 * XS_STRIDE;  // [64][102]
    const int t   = blockIdx.x;
    const int c0  = blockIdx.y * 64;
    const int tid = threadIdx.x;

    // stage x (gathered embeddings): threads 0-127 <-> batch rows
    if (tid < 128) {
        const int b = tid;
        const int token = tok[b * TT + t];
        const float4* src = (const float4*)(emb + (size_t)token * DD);
        float* dst = xs + b * XS_STRIDE;
        #pragma unroll
        for (int q = 0; q < 25; ++q) {
            float4 v = src[q];
            *(float2*)(dst + 4 * q)     = make_float2(v.x, v.y);
            *(float2*)(dst + 4 * q + 2) = make_float2(v.z, v.w);
        }
    }
    // stage weight chunk (64 cols x 100), all 256 threads
    for (int i = tid; i < 64 * 25; i += 256) {
        const int cc = i / 25, q = i - cc * 25;
        const int col = c0 + cc;
        float4 v = make_float4(0.f, 0.f, 0.f, 0.f);
        if (col < 400)      v = *(const float4*)(wih_f + col * DD + 4 * q);
        else if (col < 800) v = *(const float4*)(wih_b + (col - 400) * DD + 4 * q);
        float* dst = wc + cc * XS_STRIDE + 4 * q;
        *(float2*)(dst)     = make_float2(v.x, v.y);
        *(float2*)(dst + 2) = make_float2(v.z, v.w);
    }
    __syncthreads();

    const int ct = tid >> 5;   // warp id 0..7 -> col pairs 2ct+16j
    const int rt = tid & 31;   // rows rt + 32i

    ull acc[4][4][2];
    #pragma unroll
    for (int i = 0; i < 4; ++i)
        #pragma unroll
        for (int j = 0; j < 4; ++j) { acc[i][j][0] = 0ull; acc[i][j][1] = 0ull; }

    #pragma unroll 5
    for (int kp = 0; kp < 50; ++kp) {
        ull xv[4];
        #pragma unroll
        for (int i = 0; i < 4; ++i)
            xv[i] = *(const ull*)(xs + (rt + 32 * i) * XS_STRIDE + 2 * kp);
        ull wv[4][2];
        #pragma unroll
        for (int j = 0; j < 4; ++j) {
            #pragma unroll
            for (int e = 0; e < 2; ++e)
                wv[j][e] = *(const ull*)(wc + (2 * ct + 16 * j + e) * XS_STRIDE + 2 * kp);
        }
        #pragma unroll
        for (int i = 0; i < 4; ++i)
            #pragma unroll
            for (int j = 0; j < 4; ++j) {
                acc[i][j][0] = ffma2(xv[i], wv[j][0], acc[i][j][0]);
                acc[i][j][1] = ffma2(xv[i], wv[j][1], acc[i][j][1]);
            }
    }

    #pragma unroll
    for (int i = 0; i < 4; ++i) {
        const int b = rt + 32 * i;
        #pragma unroll
        for (int j = 0; j < 4; ++j) {
            const int col = c0 + 2 * ct + 16 * j;
            if (col < 800) {
                float2 s0 = u2f(acc[i][j][0]);
                float2 s1 = u2f(acc[i][j][1]);
                float r0 = s0.x + s0.y;
                float r1 = s1.x + s1.y;
                if (col < 400) {
                    r0 += bih_f[col] + bhh_f[col];
                    r1 += bih_f[col + 1] + bhh_f[col + 1];
                    *(float2*)(&g_gin[0][t][b][col]) = make_float2(r0, r1);
                } else {
                    const int c2 = col - 400;
                    r0 += bih_b[c2] + bhh_b[c2];
                    r1 += bih_b[c2 + 1] + bhh_b[c2 + 1];
                    *(float2*)(&g_gin[1][t][b][c2]) = make_float2(r0, r1);
                }
            }
        }
    }
}

// ================= Kernel 2: LSTM recurrence (W_hh in registers) =================
__global__ void __launch_bounds__(400, 1) k_lstm(
    const float* __restrict__ whh_f, const float* __restrict__ whh_b)
{
    __shared__ __align__(16) float hsm[208];  // interleaved: [p][ h0(2) h1(2) ]
    __shared__ float gbuf[800];

    const int dir = blockIdx.y;
    const int b0  = blockIdx.x * 2;
    const int g   = threadIdx.x;              // gate 0..399
    const float* whh = (dir ? whh_b : whh_f) + g * 100;

    ull w[50];
    #pragma unroll
    for (int q = 0; q < 50; ++q) w[q] = *(const ull*)(whh + 2 * q);

    if (g < 52) *(float4*)(hsm + 4 * g) = make_float4(0.f, 0.f, 0.f, 0.f);
    float c0v = 0.f, c1v = 0.f;
    __syncthreads();

    const int gtype = g / 100;
    int t = dir ? (TT - 1) : 0;
    const int tstep = dir ? -1 : 1;
    float pre0 = g_gin[dir][t][b0][g];
    float pre1 = g_gin[dir][t][b0 + 1][g];

    for (int s = 0; s < TT; ++s, t += tstep) {
        // unconditional clamped prefetch of next step's gin
        int tn = t + tstep;
        tn = (tn < 0) ? 0 : ((tn > TT - 1) ? TT - 1 : tn);
        float nx0 = g_gin[dir][tn][b0][g];
        float nx1 = g_gin[dir][tn][b0 + 1][g];

        ull a0a = 0ull, a0b = 0ull, a1a = 0ull, a1b = 0ull;
        #pragma unroll
        for (int q = 0; q < 50; q += 2) {
            ulonglong2 ha = *(const ulonglong2*)(hsm + 4 * q);
            ulonglong2 hb = *(const ulonglong2*)(hsm + 4 * q + 4);
            a0a = ffma2(w[q],     ha.x, a0a);
            a1a = ffma2(w[q],     ha.y, a1a);
            a0b = ffma2(w[q + 1], hb.x, a0b);
            a1b = ffma2(w[q + 1], hb.y, a1b);
        }
        float2 p0a = u2f(a0a), p0b = u2f(a0b), p1a = u2f(a1a), p1b = u2f(a1b);
        float acc0 = pre0 + (p0a.x + p0a.y) + (p0b.x + p0b.y);
        float acc1 = pre1 + (p1a.x + p1a.y) + (p1b.x + p1b.y);

        float v0, v1;
        if (gtype == 2) { v0 = tanh_fast(acc0); v1 = tanh_fast(acc1); }
        else            { v0 = sigf(acc0);      v1 = sigf(acc1); }
        gbuf[g]       = v0;
        gbuf[400 + g] = v1;
        __syncthreads();

        if (g < 100) {
            const int k = g;
            float iv = gbuf[k], fv = gbuf[k + 100], gv = gbuf[k + 200], ov = gbuf[k + 300];
            c0v = fv * c0v + iv * gv;
            float h0 = ov * tanh_fast(c0v);
            iv = gbuf[400 + k]; fv = gbuf[500 + k]; gv = gbuf[600 + k]; ov = gbuf[700 + k];
            c1v = fv * c1v + iv * gv;
            float h1 = ov * tanh_fast(c1v);
            const int p = k >> 1, e = k & 1;
            hsm[4 * p + e]     = h0;
            hsm[4 * p + 2 + e] = h1;
            g_h[dir][t][b0][k]     = h0;
            g_h[dir][t][b0 + 1][k] = h1;
        }
        pre0 = nx0; pre1 = nx1;
        __syncthreads();
    }
}

// ================= Kernel 3: emissions = [h_f|h_b] . w_tag^T + b_tag =================
#define HS_STRIDE 202
#define EMIT_SMEM ((128 * HS_STRIDE + 25 * HS_STRIDE) * 4)

__global__ void __launch_bounds__(320) k_emit(
    const float* __restrict__ wtag, const float* __restrict__ btag)
{
    extern __shared__ float esm[];
    float* hs = esm;                    // [128][202]  (rows = batch b)
    float* wt = esm + 128 * HS_STRIDE;  // [25][202]
    const int tid = threadIdx.x;
    const int t = blockIdx.x;

    for (int i = tid; i < 25 * 100; i += 320) {
        const int l = i / 100, kp = i - l * 100;
        *(float2*)(wt + l * HS_STRIDE + 2 * kp) = *(const float2*)(wtag + l * 200 + 2 * kp);
    }
    for (int i = tid; i < 128 * 100; i += 320) {
        const int b = i / 100, kp = i - b * 100;
        const int k = 2 * kp;
        float2 v = (k < 100) ? *(const float2*)(&g_h[0][t][b][k])
                             : *(const float2*)(&g_h[1][t][b][k - 100]);
        *(float2*)(hs + b * HS_STRIDE + k) = v;
    }
    __syncthreads();

    const int rp = tid / 5;       // 0..63 -> rows {2rp, 2rp+1}
    const int lg = tid - rp * 5;  // labels {5lg..5lg+4}
    ull acc[2][5];
    #pragma unroll
    for (int rr = 0; rr < 2; ++rr)
        #pragma unroll
        for (int j = 0; j < 5; ++j) acc[rr][j] = 0ull;

    const float* h0p = hs + (2 * rp) * HS_STRIDE;
    const float* h1p = hs + (2 * rp + 1) * HS_STRIDE;
    #pragma unroll 4
    for (int kp = 0; kp < 100; ++kp) {
        ull hv0 = *(const ull*)(h0p + 2 * kp);
        ull hv1 = *(const ull*)(h1p + 2 * kp);
        #pragma unroll
        for (int j = 0; j < 5; ++j) {
            ull wv = *(const ull*)(wt + (5 * lg + j) * HS_STRIDE + 2 * kp);
            acc[0][j] = ffma2(hv0, wv, acc[0][j]);
            acc[1][j] = ffma2(hv1, wv, acc[1][j]);
        }
    }
    #pragma unroll
    for (int rr = 0; rr < 2; ++rr) {
        const int b = 2 * rp + rr;
        #pragma unroll
        for (int j = 0; j < 5; ++j) {
            const int l = 5 * lg + j;
            float2 p = u2f(acc[rr][j]);
            g_em[((size_t)b * TT + t) * EMS + l] = p.x + p.y + btag[l];
        }
    }
}

// ================= Kernel 4: CRF NLL — 2 batch elems per warp, f32x2 label pairs =================
// lanes 0-15: elem b0, lanes 16-31: elem b0+1; within group, lanes gl=0..12
// own label pairs (2gl, 2gl+1); pair (24,25) has padded hi half (prob 0).
__global__ void __launch_bounds__(32) k_crf(
    const float* __restrict__ trans, const float* __restrict__ strans,
    const float* __restrict__ etrans, const int* __restrict__ tags,
    const int* __restrict__ lengths)
{
    __shared__ float tr[640];          // raw transitions (gold path)
    __shared__ ull   E2[25][16];       // exp(trans) pairs [p][j], j=0..12 (pad hi of j=12 = 0)
    __shared__ ull   As2[2][26];       // splatted scaled alpha per prev label, per elem
    __shared__ float etp[28];          // etrans padded (etp[25]=0)

    const int b0   = blockIdx.x * 2;
    const int lane = threadIdx.x;
    const int grp  = lane >> 4;        // 0 / 1
    const int gl   = lane & 15;        // lane-in-group
    const unsigned gmask = 0xFFFFu << (16 * grp);
    const int b = b0 + grp;

    for (int i = lane; i < 625; i += 32) tr[i] = trans[i];
    for (int i = lane; i < 25 * 13; i += 32) {
        const int p = i / 13, j = i - p * 13;
        float lo = __expf(tr[p * 25 + 2 * j]);
        float hi = (2 * j + 1 < 25) ? __expf(tr[p * 25 + 2 * j + 1]) : 0.f;
        E2[p][j] = f2u(lo, hi);
    }
    if (lane < 26) etp[lane] = (lane < 25) ? etrans[lane] : 0.f;
    __syncwarp();

    const int len = lengths[b];
    const int* tg = tags + b * TT;
    const float* em = g_em + (size_t)b * TT * EMS;

    // ---- gold path score (group-local, 16 lanes) ----
    float gp = 0.f;
    for (int t = 1 + gl; t < TT; t += 16) {
        if (t < len) {
            int tp = tg[t - 1], tc = tg[t];
            gp += tr[tp * 25 + tc] + em[t * EMS + tc];
        }
    }
    #pragma unroll
    for (int off = 8; off; off >>= 1) gp += __shfl_xor_sync(gmask, gp, off);
    float gold = gp;
    if (gl == 0) {
        int t0 = tg[0];
        gold += strans[t0] + em[t0];
        gold += etp[tg[len - 1]];
    }
    gold = __shfl_sync(gmask, gold, 16 * grp);

    // ---- forward algorithm, scaled-probability domain ----
    float2 A = make_float2(0.f, 0.f);
    float off = 0.f;
    if (gl < 13) {
        A.x = __expf(strans[2 * gl] + em[2 * gl]);
        if (2 * gl + 1 < 25) A.y = __expf(strans[2 * gl + 1] + em[2 * gl + 1]);
        As2[grp][2 * gl] = f2u(A.x, A.x);
        if (2 * gl + 1 < 25) As2[grp][2 * gl + 1] = f2u(A.y, A.y);
    }
    __syncwarp();

    float2 emn = make_float2(0.f, 0.f);
    if (gl < 13) emn = *(const float2*)(em + EMS + 2 * gl);   // prefetch t=1

    for (int t = 1; t < TT; ++t) {
        const float2 emc = emn;
        const int t2 = (t + 1 < TT) ? (t + 1) : t;
        if (gl < 13) emn = *(const float2*)(em + t2 * EMS + 2 * gl);

        if (t < len) {
            if (gl < 13) {
                ull accA = 0ull, accB = 0ull;
                #pragma unroll
                for (int p = 0; p < 24; p += 2) {
                    accA = ffma2(As2[grp][p],     E2[p][gl],     accA);
                    accB = ffma2(As2[grp][p + 1], E2[p + 1][gl], accB);
                }
                accA = ffma2(As2[grp][24], E2[24][gl], accA);
                ull s = fadd2(accA, accB);
                ull e = f2u(__expf(emc.x), __expf(emc.y));
                A = u2f(fmul2(s, e));
            }
            if ((t & 15) == 15) {   // periodic rescale
                float m = fmaxf(A.x, A.y);
                #pragma unroll
                for (int o = 8; o; o >>= 1)
                    m = fmaxf(m, __shfl_xor_sync(gmask, m, o));
                off += __logf(m);
                float inv = __frcp_rn(m);
                A.x *= inv; A.y *= inv;
            }
        }
        __syncwarp();
        if (gl < 13) {
            As2[grp][2 * gl] = f2u(A.x, A.x);
            if (2 * gl + 1 < 25) As2[grp][2 * gl + 1] = f2u(A.y, A.y);
        }
        __syncwarp();
    }

    float val = 0.f;
    if (gl < 13) val = A.x * __expf(etp[2 * gl]) + A.y * __expf(etp[2 * gl + 1]);
    #pragma unroll
    for (int o = 8; o; o >>= 1) val += __shfl_xor_sync(gmask, val, o);
    if (gl == 0) g_res[b] = off + __logf(val) - gold;
}

// ================= Kernel 5: final fixed-order reduction =================
__global__ void __launch_bounds__(128) k_reduce(float* __restrict__ out)
{
    __shared__ float s[128];
    s[threadIdx.x] = g_res[threadIdx.x];
    __syncthreads();
    for (int st = 64; st > 0; st >>= 1) {
        if (threadIdx.x < st) s[threadIdx.x] += s[threadIdx.x + st];
        __syncthreads();
    }
    if (threadIdx.x == 0) out[0] = s[0];
}

// ================= launch =================
extern "C" void kernel_launch(void* const* d_in, const int* in_sizes, int n_in,
                              void* d_out, int out_size)
{
    const int*   tok     = (const int*)  d_in[0];
    const int*   tag     = (const int*)  d_in[1];
    const int*   lengths = (const int*)  d_in[2];
    const float* emb     = (const float*)d_in[3];
    const float* wih_f   = (const float*)d_in[4];
    const float* whh_f   = (const float*)d_in[5];
    const float* bih_f   = (const float*)d_in[6];
    const float* bhh_f   = (const float*)d_in[7];
    const float* wih_b   = (const float*)d_in[8];
    const float* whh_b   = (const float*)d_in[9];
    const float* bih_b   = (const float*)d_in[10];
    const float* bhh_b   = (const float*)d_in[11];
    const float* wtag    = (const float*)d_in[12];
    const float* btag    = (const float*)d_in[13];
    const float* trans   = (const float*)d_in[14];
    const float* strans  = (const float*)d_in[15];
    const float* etrans  = (const float*)d_in[16];
    float* out = (float*)d_out;

    cudaFuncSetAttribute(k_input_proj, cudaFuncAttributeMaxDynamicSharedMemorySize, PROJ_SMEM);
    cudaFuncSetAttribute(k_emit, cudaFuncAttributeMaxDynamicSharedMemorySize, EMIT_SMEM);

    k_input_proj<<<dim3(512, 13), 256, PROJ_SMEM>>>(tok, emb, wih_f, wih_b,
                                                    bih_f, bhh_f, bih_b, bhh_b);
    k_lstm<<<dim3(64, 2), 400>>>(whh_f, whh_b);
    k_emit<<<512, 320, EMIT_SMEM>>>(wtag, btag);
    k_crf<<<64, 32>>>(trans, strans, etrans, tag, lengths);
    k_reduce<<<1, 128>>>(out);
}

// round 5
// speedup vs baseline: 1.5453x; 1.5453x over previous
#include <cuda_runtime.h>
#include <math.h>

#define BB 128
#define TT 512
#define DD 100
#define HH 100
#define G4 400
#define LL 25

typedef unsigned long long ull;

// ---------------- device scratch (static; no runtime allocation) ----------------
__device__ float g_gin[2][TT][BB][G4];          // input projection + biases
__device__ float g_h[2][TT][BB][HH];            // hidden states, both dirs
__device__ float g_em[(size_t)BB * TT * LL];    // emissions [b][t][l]
__device__ float g_res[BB];                     // per-batch logZ - gold

// ---------------- helpers ----------------
__device__ __forceinline__ float htanh(float x) {
    float y;
    asm("tanh.approx.f32 %0, %1;" : "=f"(y) : "f"(x));
    return y;
}
__device__ __forceinline__ float hsig(float x) {          // sigmoid via HW tanh
    return fmaf(0.5f, htanh(0.5f * x), 0.5f);
}
__device__ __forceinline__ ull ffma2(ull a, ull b, ull c) {
    ull d;
    asm("fma.rn.f32x2 %0, %1, %2, %3;" : "=l"(d) : "l"(a), "l"(b), "l"(c));
    return d;
}
__device__ __forceinline__ float2 u2f(ull u) {
    float2 f;
    asm("mov.b64 {%0, %1}, %2;" : "=f"(f.x), "=f"(f.y) : "l"(u));
    return f;
}

// ================= Kernel 1: embedding lookup + input projection GEMM =================
// 64-row x 64-col tiles, 128 threads, thread tile 4x8, f32x2 k-pair packing.
// smem 52KB -> 4 blocks/SM (16 warps/SM) for latency hiding.
#define XS_STRIDE 102
#define PROJ_SMEM ((64 * XS_STRIDE + 64 * XS_STRIDE) * 4)

__global__ void __launch_bounds__(128, 4) k_input_proj(
    const int* __restrict__ tok, const float* __restrict__ emb,
    const float* __restrict__ wih_f, const float* __restrict__ wih_b,
    const float* __restrict__ bih_f, const float* __restrict__ bhh_f,
    const float* __restrict__ bih_b, const float* __restrict__ bhh_b)
{
    extern __shared__ float psm[];
    float* xs = psm;                   // [64][102]
    float* wc = psm + 64 * XS_STRIDE;  // [64][102]
    const int m0 = blockIdx.x * 64;
    const int c0 = blockIdx.y * 64;
    const int tid = threadIdx.x;

    // stage x tile (gathered embeddings)
    for (int i = tid; i < 64 * 25; i += 128) {
        const int r = i / 25, q = i - r * 25;
        const int m = m0 + r;
        const int t = m >> 7, b = m & 127;
        const int token = tok[b * TT + t];
        float4 v = *(const float4*)(emb + (size_t)token * DD + 4 * q);
        float* dst = xs + r * XS_STRIDE + 4 * q;
        *(float2*)(dst)     = make_float2(v.x, v.y);
        *(float2*)(dst + 2) = make_float2(v.z, v.w);
    }
    // stage weight chunk (64 cols x 100)
    for (int i = tid; i < 64 * 25; i += 128) {
        const int cc = i / 25, q = i - cc * 25;
        const int col = c0 + cc;
        float4 v = make_float4(0.f, 0.f, 0.f, 0.f);
        if (col < 400)      v = *(const float4*)(wih_f + col * DD + 4 * q);
        else if (col < 800) v = *(const float4*)(wih_b + (col - 400) * DD + 4 * q);
        float* dst = wc + cc * XS_STRIDE + 4 * q;
        *(float2*)(dst)     = make_float2(v.x, v.y);
        *(float2*)(dst + 2) = make_float2(v.z, v.w);
    }
    __syncthreads();

    const int ct = tid >> 4;   // 0..7
    const int rt = tid & 15;   // rows rt + 16*i (conflict-free: (rt*6)%32 distinct)

    ull acc[4][4][2];
    #pragma unroll
    for (int i = 0; i < 4; ++i)
        #pragma unroll
        for (int j = 0; j < 4; ++j) { acc[i][j][0] = 0ull; acc[i][j][1] = 0ull; }

    #pragma unroll 2
    for (int kp = 0; kp < 50; ++kp) {
        ull xv[4];
        #pragma unroll
        for (int i = 0; i < 4; ++i)
            xv[i] = *(const ull*)(xs + (rt + 16 * i) * XS_STRIDE + 2 * kp);
        ull wv[4][2];
        #pragma unroll
        for (int j = 0; j < 4; ++j) {
            #pragma unroll
            for (int e = 0; e < 2; ++e)
                wv[j][e] = *(const ull*)(wc + (2 * ct + 16 * j + e) * XS_STRIDE + 2 * kp);
        }
        #pragma unroll
        for (int i = 0; i < 4; ++i)
            #pragma unroll
            for (int j = 0; j < 4; ++j) {
                acc[i][j][0] = ffma2(xv[i], wv[j][0], acc[i][j][0]);
                acc[i][j][1] = ffma2(xv[i], wv[j][1], acc[i][j][1]);
            }
    }

    #pragma unroll
    for (int i = 0; i < 4; ++i) {
        const int r = rt + 16 * i;
        const int m = m0 + r;
        const int t = m >> 7, b = m & 127;
        #pragma unroll
        for (int j = 0; j < 4; ++j) {
            const int col = c0 + 2 * ct + 16 * j;
            if (col < 800) {
                float2 s0 = u2f(acc[i][j][0]);
                float2 s1 = u2f(acc[i][j][1]);
                float r0 = s0.x + s0.y;
                float r1 = s1.x + s1.y;
                if (col < 400) {
                    r0 += bih_f[col] + bhh_f[col];
                    r1 += bih_f[col + 1] + bhh_f[col + 1];
                    *(float2*)(&g_gin[0][t][b][col]) = make_float2(r0, r1);
                } else {
                    const int c2 = col - 400;
                    r0 += bih_b[c2] + bhh_b[c2];
                    r1 += bih_b[c2 + 1] + bhh_b[c2 + 1];
                    *(float2*)(&g_gin[1][t][b][c2]) = make_float2(r0, r1);
                }
            }
        }
    }
}

// ================= Kernel 2: LSTM recurrence (W_hh in registers, HW tanh) =================
__global__ void __launch_bounds__(400, 1) k_lstm(
    const float* __restrict__ whh_f, const float* __restrict__ whh_b)
{
    __shared__ __align__(16) float hsm[208];  // interleaved: [p][ h0(2) h1(2) ]
    __shared__ float gbuf[800];

    const int dir = blockIdx.y;
    const int b0  = blockIdx.x * 2;
    const int g   = threadIdx.x;              // gate 0..399
    const float* whh = (dir ? whh_b : whh_f) + g * 100;

    ull w[50];
    #pragma unroll
    for (int q = 0; q < 50; ++q) w[q] = *(const ull*)(whh + 2 * q);

    if (g < 52) *(float4*)(hsm + 4 * g) = make_float4(0.f, 0.f, 0.f, 0.f);
    float cv = 0.f;                            // cell state for (elem g/100? no: pointwise owner)
    __syncthreads();

    const int gtype = g / 100;
    int t = dir ? (TT - 1) : 0;
    const int tstep = dir ? -1 : 1;
    float pre0 = g_gin[dir][t][b0][g];
    float pre1 = g_gin[dir][t][b0 + 1][g];

    // pointwise ownership: threads 0..199 -> (elem = g/100? ) e = g>=100, k = g%100
    const int pe = (g >= 100 && g < 200) ? 1 : 0;
    const int pk = g - 100 * pe;              // valid only for g<200

    for (int s = 0; s < TT; ++s, t += tstep) {
        int tn = t + tstep;
        tn = (tn < 0) ? 0 : ((tn > TT - 1) ? TT - 1 : tn);
        float nx0 = g_gin[dir][tn][b0][g];
        float nx1 = g_gin[dir][tn][b0 + 1][g];

        ull a0a = 0ull, a0b = 0ull, a1a = 0ull, a1b = 0ull;
        #pragma unroll
        for (int q = 0; q < 50; q += 2) {
            ulonglong2 ha = *(const ulonglong2*)(hsm + 4 * q);
            ulonglong2 hb = *(const ulonglong2*)(hsm + 4 * q + 4);
            a0a = ffma2(w[q],     ha.x, a0a);
            a1a = ffma2(w[q],     ha.y, a1a);
            a0b = ffma2(w[q + 1], hb.x, a0b);
            a1b = ffma2(w[q + 1], hb.y, a1b);
        }
        float2 p0a = u2f(a0a), p0b = u2f(a0b), p1a = u2f(a1a), p1b = u2f(a1b);
        float acc0 = pre0 + (p0a.x + p0a.y) + (p0b.x + p0b.y);
        float acc1 = pre1 + (p1a.x + p1a.y) + (p1b.x + p1b.y);

        float v0, v1;
        if (gtype == 2) { v0 = htanh(acc0); v1 = htanh(acc1); }
        else            { v0 = hsig(acc0);  v1 = hsig(acc1); }
        gbuf[g]       = v0;
        gbuf[400 + g] = v1;
        __syncthreads();

        if (g < 200) {
            const int base = 400 * pe;
            float iv = gbuf[base + pk],       fv = gbuf[base + pk + 100];
            float gv = gbuf[base + pk + 200], ov = gbuf[base + pk + 300];
            cv = fv * cv + iv * gv;
            float hv = ov * htanh(cv);
            hsm[4 * (pk >> 1) + 2 * pe + (pk & 1)] = hv;
            g_h[dir][t][b0 + pe][pk] = hv;
        }
        pre0 = nx0; pre1 = nx1;
        __syncthreads();
    }
}

// ================= Kernel 3: emissions = [h_f|h_b] . w_tag^T + b_tag =================
#define HS_STRIDE 202
#define EMIT_SMEM ((128 * HS_STRIDE + 25 * HS_STRIDE) * 4)

__global__ void __launch_bounds__(320) k_emit(
    const float* __restrict__ wtag, const float* __restrict__ btag)
{
    extern __shared__ float esm[];
    float* hs = esm;                    // [128][202]
    float* wt = esm + 128 * HS_STRIDE;  // [25][202]
    const int tid = threadIdx.x;
    const int m0 = blockIdx.x * 128;

    for (int i = tid; i < 25 * 100; i += 320) {
        const int l = i / 100, kp = i - l * 100;
        *(float2*)(wt + l * HS_STRIDE + 2 * kp) = *(const float2*)(wtag + l * 200 + 2 * kp);
    }
    for (int i = tid; i < 128 * 100; i += 320) {
        const int r = i / 100, kp = i - r * 100;
        const int m = m0 + r;
        const int t = m >> 7, b = m & 127;
        const int k = 2 * kp;
        float2 v = (k < 100) ? *(const float2*)(&g_h[0][t][b][k])
                             : *(const float2*)(&g_h[1][t][b][k - 100]);
        *(float2*)(hs + r * HS_STRIDE + k) = v;
    }
    __syncthreads();

    const int rp = tid / 5;       // 0..63 -> rows {2rp, 2rp+1}
    const int lg = tid - rp * 5;  // labels {5lg..5lg+4}
    ull acc[2][5];
    #pragma unroll
    for (int rr = 0; rr < 2; ++rr)
        #pragma unroll
        for (int j = 0; j < 5; ++j) acc[rr][j] = 0ull;

    const float* h0p = hs + (2 * rp) * HS_STRIDE;
    const float* h1p = hs + (2 * rp + 1) * HS_STRIDE;
    #pragma unroll 4
    for (int kp = 0; kp < 100; ++kp) {
        ull hv0 = *(const ull*)(h0p + 2 * kp);
        ull hv1 = *(const ull*)(h1p + 2 * kp);
        #pragma unroll
        for (int j = 0; j < 5; ++j) {
            ull wv = *(const ull*)(wt + (5 * lg + j) * HS_STRIDE + 2 * kp);
            acc[0][j] = ffma2(hv0, wv, acc[0][j]);
            acc[1][j] = ffma2(hv1, wv, acc[1][j]);
        }
    }
    #pragma unroll
    for (int rr = 0; rr < 2; ++rr) {
        const int r = 2 * rp + rr;
        const int m = m0 + r;
        const int t = m >> 7, b = m & 127;
        #pragma unroll
        for (int j = 0; j < 5; ++j) {
            const int l = 5 * lg + j;
            float2 p = u2f(acc[rr][j]);
            g_em[((size_t)b * TT + t) * LL + l] = p.x + p.y + btag[l];
        }
    }
}

// ================= Kernel 4: CRF NLL (scaled-probability forward algorithm) =================
__global__ void __launch_bounds__(32) k_crf(
    const float* __restrict__ trans, const float* __restrict__ strans,
    const float* __restrict__ etrans, const int* __restrict__ tags,
    const int* __restrict__ lengths)
{
    __shared__ float E[640];    // exp(transitions) [p*25 + l]
    __shared__ float tr[640];   // raw transitions (gold path)
    __shared__ float As[32];
    const int b = blockIdx.x;
    const int lane = threadIdx.x;

    for (int i = lane; i < 625; i += 32) {
        float v = trans[i];
        tr[i] = v;
        E[i] = __expf(v);
    }
    __syncwarp();

    const int len = lengths[b];
    const int* tg = tags + b * TT;
    const float* em = g_em + (size_t)b * TT * LL;

    // ---- gold path score ----
    float gp = 0.f;
    for (int t = 1 + lane; t < TT; t += 32) {
        if (t < len) {
            int tp = tg[t - 1], tc = tg[t];
            gp += tr[tp * 25 + tc] + em[t * LL + tc];
        }
    }
    #pragma unroll
    for (int off = 16; off; off >>= 1) gp += __shfl_down_sync(0xffffffffu, gp, off);
    float gold = __shfl_sync(0xffffffffu, gp, 0);
    if (lane == 0) {
        int t0 = tg[0];
        gold += strans[t0] + em[t0];
        gold += etrans[tg[len - 1]];
    }
    gold = __shfl_sync(0xffffffffu, gold, 0);

    // ---- forward algorithm in scaled-prob domain ----
    float A = 0.f, off = 0.f;
    if (lane < LL) A = __expf(strans[lane] + em[lane]);
    As[lane] = A;
    __syncwarp();

    float emn = (lane < LL) ? em[LL + lane] : 0.f;   // prefetch t=1
    for (int t = 1; t < TT; ++t) {
        const float emc = emn;
        const int t2 = (t + 1 < TT) ? (t + 1) : t;
        emn = (lane < LL) ? em[t2 * LL + lane] : 0.f;

        if (t < len) {
            float sa = 0.f, sb = 0.f;
            #pragma unroll
            for (int p = 0; p < 24; p += 2) {
                sa = fmaf(As[p],     E[p * 25 + lane],       sa);
                sb = fmaf(As[p + 1], E[(p + 1) * 25 + lane], sb);
            }
            sa = fmaf(As[24], E[24 * 25 + lane], sa);
            A = (sa + sb) * __expf(emc);
        }
        if ((t & 15) == 15) {   // periodic rescale (growth < e^52 per 16 steps)
            float m = A;
            #pragma unroll
            for (int o = 16; o; o >>= 1) m = fmaxf(m, __shfl_xor_sync(0xffffffffu, m, o));
            off += __logf(m);
            A = __fdividef(A, m);
        }
        __syncwarp();
        As[lane] = A;
        __syncwarp();
    }

    float val = (lane < LL) ? A * __expf(etrans[lane]) : 0.f;
    #pragma unroll
    for (int o = 16; o; o >>= 1) val += __shfl_xor_sync(0xffffffffu, val, o);
    float logZ = off + __logf(val);
    if (lane == 0) g_res[b] = logZ - gold;
}

// ================= Kernel 5: final fixed-order reduction =================
__global__ void __launch_bounds__(128) k_reduce(float* __restrict__ out)
{
    __shared__ float s[128];
    s[threadIdx.x] = g_res[threadIdx.x];
    __syncthreads();
    for (int st = 64; st > 0; st >>= 1) {
        if (threadIdx.x < st) s[threadIdx.x] += s[threadIdx.x + st];
        __syncthreads();
    }
    if (threadIdx.x == 0) out[0] = s[0];
}

// ================= launch =================
extern "C" void kernel_launch(void* const* d_in, const int* in_sizes, int n_in,
                              void* d_out, int out_size)
{
    const int*   tok     = (const int*)  d_in[0];
    const int*   tag     = (const int*)  d_in[1];
    const int*   lengths = (const int*)  d_in[2];
    const float* emb     = (const float*)d_in[3];
    const float* wih_f   = (const float*)d_in[4];
    const float* whh_f   = (const float*)d_in[5];
    const float* bih_f   = (const float*)d_in[6];
    const float* bhh_f   = (const float*)d_in[7];
    const float* wih_b   = (const float*)d_in[8];
    const float* whh_b   = (const float*)d_in[9];
    const float* bih_b   = (const float*)d_in[10];
    const float* bhh_b   = (const float*)d_in[11];
    const float* wtag    = (const float*)d_in[12];
    const float* btag    = (const float*)d_in[13];
    const float* trans   = (const float*)d_in[14];
    const float* strans  = (const float*)d_in[15];
    const float* etrans  = (const float*)d_in[16];
    float* out = (float*)d_out;

    cudaFuncSetAttribute(k_input_proj, cudaFuncAttributeMaxDynamicSharedMemorySize, PROJ_SMEM);
    cudaFuncSetAttribute(k_emit, cudaFuncAttributeMaxDynamicSharedMemorySize, EMIT_SMEM);

    k_input_proj<<<dim3(1024, 13), 128, PROJ_SMEM>>>(tok, emb, wih_f, wih_b,
                                                     bih_f, bhh_f, bih_b, bhh_b);
    k_lstm<<<dim3(64, 2), 400>>>(whh_f, whh_b);
    k_emit<<<512, 320, EMIT_SMEM>>>(wtag, btag);
    k_crf<<<128, 32>>>(trans, strans, etrans, tag, lengths);
    k_reduce<<<1, 128>>>(out);
}